// round 1
// baseline (speedup 1.0000x reference)
#include <cuda_runtime.h>
#include <math.h>

#define B_  2
#define L_  2048
#define D_  1024
#define H_  16
#define DH_ 64
#define R_  (B_ * L_)          // 4096 rows total
#define D3_ (3 * D_)           // 3072

// ---------------- scratch (device globals; no allocation allowed) -----------
__device__ float g_h[(size_t)R_ * D_];        // 16 MB  : LN1 output
__device__ float g_qkv[(size_t)R_ * D3_];     // 48 MB  : qkv (q/k rewritten in place)
__device__ float g_ctx[(size_t)R_ * D_];      // 16 MB  : attention context
__device__ float g_cos[L_ * 32];
__device__ float g_sin[L_ * 32];

// ---------------- RoPE table (double for accuracy; fp32 angle like ref) -----
__global__ void rope_tab_kernel() {
    int l = blockIdx.x;          // 0..2047
    int j = threadIdx.x;         // 0..31
    // inv_freq = 10000^(-(2j)/64) = 10000^(-j/32), rounded to fp32 like the ref
    float inv_f = (float)pow(10000.0, -(double)j / 32.0);
    float ang_f = (float)l * inv_f;              // fp32 product, matching jnp fp32
    double a = (double)ang_f;
    g_cos[l * 32 + j] = (float)cos(a);
    g_sin[l * 32 + j] = (float)sin(a);
}

// ---------------- LN1: one block per row, 256 threads ----------------------
__global__ void __launch_bounds__(256) ln1_kernel(const float* __restrict__ x,
                                                  const float* __restrict__ w,
                                                  const float* __restrict__ b) {
    __shared__ float sa[8], sb[8];
    int row = blockIdx.x;
    int t = threadIdx.x;
    const float4* xr = (const float4*)(x + (size_t)row * D_);
    float4 v = xr[t];
    float s  = v.x + v.y + v.z + v.w;
    float ss = v.x * v.x + v.y * v.y + v.z * v.z + v.w * v.w;
#pragma unroll
    for (int o = 16; o > 0; o >>= 1) {
        s  += __shfl_xor_sync(0xffffffffu, s, o);
        ss += __shfl_xor_sync(0xffffffffu, ss, o);
    }
    if ((t & 31) == 0) { sa[t >> 5] = s; sb[t >> 5] = ss; }
    __syncthreads();
    float ts = 0.f, tss = 0.f;
#pragma unroll
    for (int i = 0; i < 8; i++) { ts += sa[i]; tss += sb[i]; }
    float mu  = ts * (1.0f / D_);
    float var = tss * (1.0f / D_) - mu * mu;
    float rs  = rsqrtf(var + 1e-5f);
    float4 wv = ((const float4*)w)[t];
    float4 bv = ((const float4*)b)[t];
    float4 o;
    o.x = (v.x - mu) * rs * wv.x + bv.x;
    o.y = (v.y - mu) * rs * wv.y + bv.y;
    o.z = (v.z - mu) * rs * wv.z + bv.z;
    o.w = (v.w - mu) * rs * wv.w + bv.w;
    ((float4*)(g_h + (size_t)row * D_))[t] = o;
}

// ---------------- q/k LayerNorm + RoPE (in place on g_qkv) -----------------
__global__ void __launch_bounds__(256) qkln_rope_kernel(const float* __restrict__ qw,
                                                        const float* __restrict__ kw) {
    __shared__ float sa[8], sb[8];
    __shared__ float sv[D_];
    int row   = blockIdx.x;
    int which = blockIdx.y;          // 0 = q, 1 = k
    int t = threadIdx.x;
    float* base = g_qkv + (size_t)row * D3_ + which * D_;
    const float* w = which ? kw : qw;

    float4 v = ((const float4*)base)[t];
    float s  = v.x + v.y + v.z + v.w;
    float ss = v.x * v.x + v.y * v.y + v.z * v.z + v.w * v.w;
#pragma unroll
    for (int o = 16; o > 0; o >>= 1) {
        s  += __shfl_xor_sync(0xffffffffu, s, o);
        ss += __shfl_xor_sync(0xffffffffu, ss, o);
    }
    if ((t & 31) == 0) { sa[t >> 5] = s; sb[t >> 5] = ss; }
    __syncthreads();
    float ts = 0.f, tss = 0.f;
#pragma unroll
    for (int i = 0; i < 8; i++) { ts += sa[i]; tss += sb[i]; }
    float mu  = ts * (1.0f / D_);
    float var = tss * (1.0f / D_) - mu * mu;
    float rs  = rsqrtf(var + 1e-5f);
    float4 wv = ((const float4*)w)[t];
    sv[4 * t + 0] = (v.x - mu) * rs * wv.x;
    sv[4 * t + 1] = (v.y - mu) * rs * wv.y;
    sv[4 * t + 2] = (v.z - mu) * rs * wv.z;
    sv[4 * t + 3] = (v.w - mu) * rs * wv.w;
    __syncthreads();

    int l = row & (L_ - 1);
#pragma unroll
    for (int c = 0; c < 4; c++) {
        int col = 4 * t + c;
        int d   = col & 63;
        int dd  = d & 31;
        float cs = g_cos[l * 32 + dd];
        float sn = g_sin[l * 32 + dd];
        float y = sv[col];
        float res;
        if (d < 32) res = y * cs - sv[col + 32] * sn;
        else        res = y * cs + sv[col - 32] * sn;
        base[col] = res;
    }
}

// ---------------- 128x128x8 register-blocked SGEMM body --------------------
__device__ __forceinline__ void sgemm_body(const float* __restrict__ A,
                                           const float* __restrict__ Bm,
                                           float* __restrict__ C,
                                           int N, int K) {
    __shared__ float As[8][128];
    __shared__ float Bs[8][128];
    int tid = threadIdx.x;
    int tx = tid & 15, ty = tid >> 4;
    int m0 = blockIdx.y * 128, n0 = blockIdx.x * 128;
    int ar = tid >> 1, ac = (tid & 1) * 4;
    int br = tid >> 5, bc = (tid & 31) * 4;
    const float* Aload = A + (size_t)(m0 + ar) * K + ac;
    const float* Bload = Bm + (size_t)br * N + n0 + bc;

    float acc[8][8];
#pragma unroll
    for (int i = 0; i < 8; i++)
#pragma unroll
        for (int j = 0; j < 8; j++) acc[i][j] = 0.f;

    for (int kt = 0; kt < K; kt += 8) {
        float4 av = *(const float4*)(Aload + kt);
        float4 bv = *(const float4*)(Bload + (size_t)kt * N);
        __syncthreads();
        As[ac + 0][ar] = av.x;
        As[ac + 1][ar] = av.y;
        As[ac + 2][ar] = av.z;
        As[ac + 3][ar] = av.w;
        *(float4*)&Bs[br][bc] = bv;
        __syncthreads();
#pragma unroll
        for (int k = 0; k < 8; k++) {
            float4 a0 = *(const float4*)&As[k][ty * 8];
            float4 a1 = *(const float4*)&As[k][ty * 8 + 4];
            float4 b0 = *(const float4*)&Bs[k][tx * 8];
            float4 b1 = *(const float4*)&Bs[k][tx * 8 + 4];
            float a[8] = {a0.x, a0.y, a0.z, a0.w, a1.x, a1.y, a1.z, a1.w};
            float bb[8] = {b0.x, b0.y, b0.z, b0.w, b1.x, b1.y, b1.z, b1.w};
#pragma unroll
            for (int i = 0; i < 8; i++)
#pragma unroll
                for (int j = 0; j < 8; j++)
                    acc[i][j] = fmaf(a[i], bb[j], acc[i][j]);
        }
    }
#pragma unroll
    for (int i = 0; i < 8; i++) {
        float* crow = C + (size_t)(m0 + ty * 8 + i) * N + n0 + tx * 8;
        *(float4*)crow       = make_float4(acc[i][0], acc[i][1], acc[i][2], acc[i][3]);
        *(float4*)(crow + 4) = make_float4(acc[i][4], acc[i][5], acc[i][6], acc[i][7]);
    }
}

__global__ void __launch_bounds__(256) gemm_qkv_kernel(const float* __restrict__ W) {
    sgemm_body(g_h, W, g_qkv, D3_, D_);
}
__global__ void __launch_bounds__(256) gemm_out_kernel(const float* __restrict__ W,
                                                       float* __restrict__ out) {
    sgemm_body(g_ctx, W, out, D_, D_);
}

// ---------------- flash attention: 64x64 tiles, 64 threads, 8x8 frags ------
#define AP 64   // smem pitch (floats)

__global__ void __launch_bounds__(64) attn_kernel(const int* __restrict__ seq_id) {
    __shared__ float Qs[64 * AP];    // transposed: Qs[d][q]
    __shared__ float KPs[64 * AP];   // K transposed [d][k]; reused as P^T [k][q]
    __shared__ float Vs[64 * AP];    // natural:    Vs[k][d]

    int qt = blockIdx.x, h = blockIdx.y, b = blockIdx.z;
    int tid = threadIdx.x;
    int tx = tid & 7, ty = tid >> 3;
    int rowBase = ty * 8, colBase = tx * 8;
    int q0 = qt * 64;
    size_t rowOff = (size_t)b * L_;

    // load Q tile transposed: thread = q column
    {
        const float4* src = (const float4*)(g_qkv + (rowOff + q0 + tid) * D3_ + h * DH_);
#pragma unroll
        for (int f = 0; f < 16; f++) {
            float4 v = src[f];
            Qs[(f * 4 + 0) * AP + tid] = v.x;
            Qs[(f * 4 + 1) * AP + tid] = v.y;
            Qs[(f * 4 + 2) * AP + tid] = v.z;
            Qs[(f * 4 + 3) * AP + tid] = v.w;
        }
    }
    int qs_r[8];
#pragma unroll
    for (int i = 0; i < 8; i++) qs_r[i] = seq_id[b * L_ + q0 + rowBase + i];

    float O[8][8];
    float m[8], lsum[8];
#pragma unroll
    for (int i = 0; i < 8; i++) {
        m[i] = -1e30f; lsum[i] = 0.f;
#pragma unroll
        for (int j = 0; j < 8; j++) O[i][j] = 0.f;
    }

    for (int kt = 0; kt < L_ / 64; kt++) {
        __syncthreads();   // prior PV done with KPs/Vs; Q stores visible (iter 0)
        // K tile transposed: thread = k column
        {
            const float4* ksrc =
                (const float4*)(g_qkv + (rowOff + kt * 64 + tid) * D3_ + D_ + h * DH_);
#pragma unroll
            for (int f = 0; f < 16; f++) {
                float4 v = ksrc[f];
                KPs[(f * 4 + 0) * AP + tid] = v.x;
                KPs[(f * 4 + 1) * AP + tid] = v.y;
                KPs[(f * 4 + 2) * AP + tid] = v.z;
                KPs[(f * 4 + 3) * AP + tid] = v.w;
            }
            // V tile natural, coalesced
#pragma unroll
            for (int f = 0; f < 16; f++) {
                int g = f * 64 + tid;
                int kk = g >> 4, c4 = g & 15;
                float4 v = ((const float4*)(g_qkv + (rowOff + kt * 64 + kk) * D3_ +
                                            2 * D_ + h * DH_))[c4];
                ((float4*)(Vs + kk * AP))[c4] = v;
            }
        }
        int ks_r[8];
#pragma unroll
        for (int j = 0; j < 8; j++) ks_r[j] = seq_id[b * L_ + kt * 64 + colBase + j];
        __syncthreads();

        // S = Q K^T (contraction over d)
        float S[8][8];
#pragma unroll
        for (int i = 0; i < 8; i++)
#pragma unroll
            for (int j = 0; j < 8; j++) S[i][j] = 0.f;
#pragma unroll 16
        for (int d = 0; d < 64; d++) {
            float4 a0 = *(const float4*)&Qs[d * AP + rowBase];
            float4 a1 = *(const float4*)&Qs[d * AP + rowBase + 4];
            float4 b0 = *(const float4*)&KPs[d * AP + colBase];
            float4 b1 = *(const float4*)&KPs[d * AP + colBase + 4];
            float a[8]  = {a0.x, a0.y, a0.z, a0.w, a1.x, a1.y, a1.z, a1.w};
            float bb[8] = {b0.x, b0.y, b0.z, b0.w, b1.x, b1.y, b1.z, b1.w};
#pragma unroll
            for (int i = 0; i < 8; i++)
#pragma unroll
                for (int j = 0; j < 8; j++)
                    S[i][j] = fmaf(a[i], bb[j], S[i][j]);
        }
        // scale + mask
#pragma unroll
        for (int i = 0; i < 8; i++)
#pragma unroll
            for (int j = 0; j < 8; j++) {
                float sc = S[i][j] * 0.125f;     // 1/sqrt(64)
                S[i][j] = (qs_r[i] == ks_r[j]) ? sc : -1e30f;
            }
        // online softmax
#pragma unroll
        for (int i = 0; i < 8; i++) {
            float mx = -1e30f;
#pragma unroll
            for (int j = 0; j < 8; j++) mx = fmaxf(mx, S[i][j]);
#pragma unroll
            for (int o = 4; o > 0; o >>= 1)
                mx = fmaxf(mx, __shfl_xor_sync(0xffffffffu, mx, o, 8));
            float mn = fmaxf(m[i], mx);
            float alpha = __expf(m[i] - mn);
            m[i] = mn;
            float rs = 0.f;
#pragma unroll
            for (int j = 0; j < 8; j++) {
                float p = (S[i][j] <= -1e29f) ? 0.f : __expf(S[i][j] - mn);
                S[i][j] = p;
                rs += p;
            }
#pragma unroll
            for (int o = 4; o > 0; o >>= 1)
                rs += __shfl_xor_sync(0xffffffffu, rs, o, 8);
            lsum[i] = lsum[i] * alpha + rs;
#pragma unroll
            for (int j = 0; j < 8; j++) O[i][j] *= alpha;
        }
        __syncthreads();   // everyone done reading KPs (K) before overwrite with P^T
#pragma unroll
        for (int j = 0; j < 8; j++) {
            *(float4*)&KPs[(colBase + j) * AP + rowBase] =
                make_float4(S[0][j], S[1][j], S[2][j], S[3][j]);
            *(float4*)&KPs[(colBase + j) * AP + rowBase + 4] =
                make_float4(S[4][j], S[5][j], S[6][j], S[7][j]);
        }
        __syncthreads();
        // O += P V (contraction over k)
#pragma unroll 16
        for (int k = 0; k < 64; k++) {
            float4 a0 = *(const float4*)&KPs[k * AP + rowBase];
            float4 a1 = *(const float4*)&KPs[k * AP + rowBase + 4];
            float4 b0 = *(const float4*)&Vs[k * AP + colBase];
            float4 b1 = *(const float4*)&Vs[k * AP + colBase + 4];
            float a[8]  = {a0.x, a0.y, a0.z, a0.w, a1.x, a1.y, a1.z, a1.w};
            float bb[8] = {b0.x, b0.y, b0.z, b0.w, b1.x, b1.y, b1.z, b1.w};
#pragma unroll
            for (int i = 0; i < 8; i++)
#pragma unroll
                for (int j = 0; j < 8; j++)
                    O[i][j] = fmaf(a[i], bb[j], O[i][j]);
        }
    }
    // epilogue: normalize and write ctx
#pragma unroll
    for (int i = 0; i < 8; i++) {
        float inv = 1.0f / lsum[i];
        float* dst = g_ctx + (rowOff + q0 + rowBase + i) * D_ + h * DH_ + colBase;
        *(float4*)dst       = make_float4(O[i][0] * inv, O[i][1] * inv,
                                          O[i][2] * inv, O[i][3] * inv);
        *(float4*)(dst + 4) = make_float4(O[i][4] * inv, O[i][5] * inv,
                                          O[i][6] * inv, O[i][7] * inv);
    }
}

// ---------------- launch ----------------------------------------------------
extern "C" void kernel_launch(void* const* d_in, const int* in_sizes, int n_in,
                              void* d_out, int out_size) {
    const float* x    = (const float*)d_in[0];
    const int*   seq  = (const int*)d_in[1];
    const float* ln1w = (const float*)d_in[2];
    const float* ln1b = (const float*)d_in[3];
    const float* wqkv = (const float*)d_in[4];
    const float* qlnw = (const float*)d_in[5];
    const float* klnw = (const float*)d_in[6];
    const float* wout = (const float*)d_in[7];
    float* out = (float*)d_out;

    rope_tab_kernel<<<L_, 32>>>();
    ln1_kernel<<<R_, 256>>>(x, ln1w, ln1b);
    gemm_qkv_kernel<<<dim3(D3_ / 128, R_ / 128), 256>>>(wqkv);
    qkln_rope_kernel<<<dim3(R_, 2), 256>>>(qlnw, klnw);
    attn_kernel<<<dim3(L_ / 64, H_, B_), 64>>>(seq);
    gemm_out_kernel<<<dim3(D_ / 128, R_ / 128), 256>>>(wout, out);
}

// round 3
// speedup vs baseline: 1.5819x; 1.5819x over previous
#include <cuda_runtime.h>
#include <math.h>
#include <stdint.h>

#define B_  2
#define L_  2048
#define D_  1024
#define H_  16
#define DH_ 64
#define R_  (B_ * L_)          // 4096 rows total
#define D3_ (3 * D_)           // 3072

// ---------------- scratch (device globals; no allocation allowed) -----------
__device__ float g_h[(size_t)R_ * D_];        // 16 MB  : LN1 output
__device__ float g_qkv[(size_t)R_ * D3_];     // 48 MB  : qkv (q/k rewritten in place)
__device__ float g_ctx[(size_t)R_ * D_];      // 16 MB  : attention context
__device__ float g_cos[L_ * 32];
__device__ float g_sin[L_ * 32];

// ---------------- helpers ---------------------------------------------------
// tf32 round: cvt.rna.tf32.f32 needs a b32 destination register.
__device__ __forceinline__ float to_tf32(float x) {
    uint32_t u;
    asm("cvt.rna.tf32.f32 %0, %1;" : "=r"(u) : "f"(x));
    return __uint_as_float(u);
}

// m16n8k8 tf32 mma, fp32 accumulate. A row-major frag {a0..a3}, B col-major {b0,b1}.
__device__ __forceinline__ void mma8(float acc[4], float4 a, float2 b) {
    uint32_t A0 = __float_as_uint(a.x), A1 = __float_as_uint(a.y);
    uint32_t A2 = __float_as_uint(a.z), A3 = __float_as_uint(a.w);
    uint32_t B0 = __float_as_uint(b.x), B1 = __float_as_uint(b.y);
    asm volatile(
        "mma.sync.aligned.m16n8k8.row.col.f32.tf32.tf32.f32 "
        "{%0,%1,%2,%3}, {%4,%5,%6,%7}, {%8,%9}, {%0,%1,%2,%3};\n"
        : "+f"(acc[0]), "+f"(acc[1]), "+f"(acc[2]), "+f"(acc[3])
        : "r"(A0), "r"(A1), "r"(A2), "r"(A3), "r"(B0), "r"(B1));
}

// ---------------- RoPE table (double for accuracy; fp32 angle like ref) -----
__global__ void rope_tab_kernel() {
    int l = blockIdx.x;
    int j = threadIdx.x;
    float inv_f = (float)pow(10000.0, -(double)j / 32.0);
    float ang_f = (float)l * inv_f;
    double a = (double)ang_f;
    g_cos[l * 32 + j] = (float)cos(a);
    g_sin[l * 32 + j] = (float)sin(a);
}

// ---------------- LN1: one block per row, 256 threads ----------------------
__global__ void __launch_bounds__(256) ln1_kernel(const float* __restrict__ x,
                                                  const float* __restrict__ w,
                                                  const float* __restrict__ b) {
    __shared__ float sa[8], sb[8];
    int row = blockIdx.x;
    int t = threadIdx.x;
    const float4* xr = (const float4*)(x + (size_t)row * D_);
    float4 v = xr[t];
    float s  = v.x + v.y + v.z + v.w;
    float ss = v.x * v.x + v.y * v.y + v.z * v.z + v.w * v.w;
#pragma unroll
    for (int o = 16; o > 0; o >>= 1) {
        s  += __shfl_xor_sync(0xffffffffu, s, o);
        ss += __shfl_xor_sync(0xffffffffu, ss, o);
    }
    if ((t & 31) == 0) { sa[t >> 5] = s; sb[t >> 5] = ss; }
    __syncthreads();
    float ts = 0.f, tss = 0.f;
#pragma unroll
    for (int i = 0; i < 8; i++) { ts += sa[i]; tss += sb[i]; }
    float mu  = ts * (1.0f / D_);
    float var = tss * (1.0f / D_) - mu * mu;
    float rs  = rsqrtf(var + 1e-5f);
    float4 wv = ((const float4*)w)[t];
    float4 bv = ((const float4*)b)[t];
    float4 o;
    o.x = (v.x - mu) * rs * wv.x + bv.x;
    o.y = (v.y - mu) * rs * wv.y + bv.y;
    o.z = (v.z - mu) * rs * wv.z + bv.z;
    o.w = (v.w - mu) * rs * wv.w + bv.w;
    ((float4*)(g_h + (size_t)row * D_))[t] = o;
}

// ---------------- q/k LayerNorm + RoPE (in place on g_qkv) -----------------
__global__ void __launch_bounds__(256) qkln_rope_kernel(const float* __restrict__ qw,
                                                        const float* __restrict__ kw) {
    __shared__ float sa[8], sb[8];
    __shared__ float sv[D_];
    int row   = blockIdx.x;
    int which = blockIdx.y;
    int t = threadIdx.x;
    float* base = g_qkv + (size_t)row * D3_ + which * D_;
    const float* w = which ? kw : qw;

    float4 v = ((const float4*)base)[t];
    float s  = v.x + v.y + v.z + v.w;
    float ss = v.x * v.x + v.y * v.y + v.z * v.z + v.w * v.w;
#pragma unroll
    for (int o = 16; o > 0; o >>= 1) {
        s  += __shfl_xor_sync(0xffffffffu, s, o);
        ss += __shfl_xor_sync(0xffffffffu, ss, o);
    }
    if ((t & 31) == 0) { sa[t >> 5] = s; sb[t >> 5] = ss; }
    __syncthreads();
    float ts = 0.f, tss = 0.f;
#pragma unroll
    for (int i = 0; i < 8; i++) { ts += sa[i]; tss += sb[i]; }
    float mu  = ts * (1.0f / D_);
    float var = tss * (1.0f / D_) - mu * mu;
    float rs  = rsqrtf(var + 1e-5f);
    float4 wv = ((const float4*)w)[t];
    sv[4 * t + 0] = (v.x - mu) * rs * wv.x;
    sv[4 * t + 1] = (v.y - mu) * rs * wv.y;
    sv[4 * t + 2] = (v.z - mu) * rs * wv.z;
    sv[4 * t + 3] = (v.w - mu) * rs * wv.w;
    __syncthreads();

    int l = row & (L_ - 1);
#pragma unroll
    for (int c = 0; c < 4; c++) {
        int col = 4 * t + c;
        int d   = col & 63;
        int dd  = d & 31;
        float cs = g_cos[l * 32 + dd];
        float sn = g_sin[l * 32 + dd];
        float y = sv[col];
        float res;
        if (d < 32) res = y * cs - sv[col + 32] * sn;
        else        res = y * cs + sv[col - 32] * sn;
        base[col] = res;
    }
}

// ---------------- TF32 tensor-core GEMM: 128x128 tile, kchunk 16 -----------
// Packed smem layouts (fragment-major):
//   Ap[mtile(8)][kstep(2)][lane*4+reg]   (A-frag = 1 LDS.128)
//   Bp[kstep(2)][ntile(16)][lane*2+reg]  (B-frag = 1 LDS.64)
__device__ __forceinline__ void gemm_ldg(const float* __restrict__ A,
                                         const float* __restrict__ Bm,
                                         int N, int K, int m0, int n0, int kt,
                                         int tid, float4 va[2], float4 vb[2]) {
#pragma unroll
    for (int j = 0; j < 2; j++) {
        int id = tid * 2 + j;
        int r = id >> 2, c = (id & 3) * 4;
        va[j] = *(const float4*)(A + (size_t)(m0 + r) * K + kt + c);
        int k = id >> 5, n = (id & 31) * 4;
        vb[j] = *(const float4*)(Bm + (size_t)(kt + k) * N + n0 + n);
    }
}

__device__ __forceinline__ void gemm_sts(float* Ap, float* Bp, int tid,
                                         const float4 va[2], const float4 vb[2]) {
#pragma unroll
    for (int j = 0; j < 2; j++) {
        int id = tid * 2 + j;
        {
            int r = id >> 2, c = (id & 3) * 4;
            const float* f = (const float*)&va[j];
#pragma unroll
            for (int cc = 0; cc < 4; cc++) {
                int cp = c + cc;
                int idx = (((r >> 4) * 2 + (cp >> 3)) << 7)
                        + (((r & 7) << 2) + (cp & 3)) * 4
                        + ((r >> 3) & 1) + (((cp >> 2) & 1) << 1);
                Ap[idx] = to_tf32(f[cc]);
            }
        }
        {
            int k = id >> 5, n = (id & 31) * 4;
            const float* f = (const float*)&vb[j];
#pragma unroll
            for (int cc = 0; cc < 4; cc++) {
                int np = n + cc;
                int idx = (((k >> 3) * 16 + (np >> 3)) << 6)
                        + (((np & 7) << 2) + (k & 3)) * 2 + ((k >> 2) & 1);
                Bp[idx] = to_tf32(f[cc]);
            }
        }
    }
}

__device__ __forceinline__ void sgemm_tc_body(const float* __restrict__ A,
                                              const float* __restrict__ Bm,
                                              float* __restrict__ C,
                                              int N, int K) {
    __shared__ float Ap[2][2048];
    __shared__ float Bp[2][2048];
    int tid = threadIdx.x, wid = tid >> 5, lane = tid & 31;
    int warp_m = wid >> 1, warp_n = wid & 1;
    int m0 = blockIdx.y * 128, n0 = blockIdx.x * 128;

    float acc[2][8][4] = {};
    float4 va[2], vb[2];
    gemm_ldg(A, Bm, N, K, m0, n0, 0, tid, va, vb);
    gemm_sts(Ap[0], Bp[0], tid, va, vb);

    int nch = K / 16;
    for (int c = 0; c < nch; c++) {
        if (c + 1 < nch) gemm_ldg(A, Bm, N, K, m0, n0, (c + 1) * 16, tid, va, vb);
        __syncthreads();
        const float* ap = Ap[c & 1];
        const float* bp = Bp[c & 1];
#pragma unroll
        for (int ks = 0; ks < 2; ks++) {
            float4 a0 = *(const float4*)&ap[(((warp_m * 2 + 0) * 2 + ks) << 7) + lane * 4];
            float4 a1 = *(const float4*)&ap[(((warp_m * 2 + 1) * 2 + ks) << 7) + lane * 4];
#pragma unroll
            for (int nt = 0; nt < 8; nt++) {
                float2 b = *(const float2*)&bp[((ks * 16 + warp_n * 8 + nt) << 6) + lane * 2];
                mma8(acc[0][nt], a0, b);
                mma8(acc[1][nt], a1, b);
            }
        }
        if (c + 1 < nch) gemm_sts(Ap[(c + 1) & 1], Bp[(c + 1) & 1], tid, va, vb);
    }
    // epilogue
#pragma unroll
    for (int mt = 0; mt < 2; mt++) {
        int r0 = m0 + warp_m * 32 + mt * 16 + (lane >> 2);
        int cc = n0 + warp_n * 64 + (lane & 3) * 2;
#pragma unroll
        for (int nt = 0; nt < 8; nt++) {
            *(float2*)(C + (size_t)r0 * N + cc + nt * 8) =
                make_float2(acc[mt][nt][0], acc[mt][nt][1]);
            *(float2*)(C + (size_t)(r0 + 8) * N + cc + nt * 8) =
                make_float2(acc[mt][nt][2], acc[mt][nt][3]);
        }
    }
}

__global__ void __launch_bounds__(256) gemm_qkv_kernel(const float* __restrict__ W) {
    sgemm_tc_body(g_h, W, g_qkv, D3_, D_);
}
__global__ void __launch_bounds__(256) gemm_out_kernel(const float* __restrict__ W,
                                                       float* __restrict__ out) {
    sgemm_tc_body(g_ctx, W, out, D_, D_);
}

// ---------------- flash attention with tf32 mma, 64x64 tiles, 128 threads --
// smem (dynamic):
//   Qp [4 mtile][8 kstep][128]  A-frag packed   4096 f
//   Kp [8 kstep(d)][8 ntile(kpos)][64] B-frag   4096 f
//   Vp [8 kstep(kpos)][8 ntile(d)][64] B-frag   4096 f
//   Pp [4 warp][8 kstep(kpos)][128] A-frag      4096 f
//   kseq[64] int
__global__ void __launch_bounds__(128) attn_tc_kernel(const int* __restrict__ seq_id) {
    extern __shared__ float smA[];
    float* Qp = smA;
    float* Kp = smA + 4096;
    float* Vp = smA + 8192;
    float* Pp = smA + 12288;
    int*  kseq = (int*)(smA + 16384);

    int qt = blockIdx.x, h = blockIdx.y, b = blockIdx.z;
    int tid = threadIdx.x, wid = tid >> 5, lane = tid & 31;
    int q0 = qt * 64;
    size_t rowOff = (size_t)b * L_;
    const float* qbase = g_qkv + (rowOff + q0) * D3_ + h * DH_;

    // pack Q tile into A-frag layout (coalesced LDG, scalar STS)
    for (int e = tid; e < 4096; e += 128) {
        int q = e >> 6, d = e & 63;
        float v = qbase[(size_t)q * D3_ + d];
        Qp[((q >> 4) * 8 + (d >> 3)) * 128 + (((q & 7) << 2) + (d & 3)) * 4
           + ((q >> 3) & 1) + (((d >> 2) & 1) << 1)] = to_tf32(v);
    }
    int qs0 = seq_id[b * L_ + q0 + wid * 16 + (lane >> 2)];
    int qs1 = seq_id[b * L_ + q0 + wid * 16 + (lane >> 2) + 8];

    float O[8][4] = {};
    float m0v = -1e30f, m1v = -1e30f, l0 = 0.f, l1 = 0.f;

    int c0 = (lane & 3) * 2;
    int lA = (lane >> 2) * 4 + (c0 & 3);
    int rA = ((c0 >> 2) & 1) << 1;
    int lB = (lane >> 2) * 4 + ((c0 + 1) & 3);
    int rB = (((c0 + 1) >> 2) & 1) << 1;

    for (int kt = 0; kt < L_ / 64; kt++) {
        __syncthreads();
        const float* kbase = g_qkv + (rowOff + kt * 64) * D3_ + D_ + h * DH_;
        const float* vbase = kbase + D_;
        for (int e = tid; e < 4096; e += 128) {
            int kp = e >> 6, d = e & 63;
            Kp[((d >> 3) * 8 + (kp >> 3)) * 64 + ((kp & 7) * 4 + (d & 3)) * 2
               + ((d >> 2) & 1)] = to_tf32(kbase[(size_t)kp * D3_ + d]);
            Vp[((kp >> 3) * 8 + (d >> 3)) * 64 + ((d & 7) * 4 + (kp & 3)) * 2
               + ((kp >> 2) & 1)] = to_tf32(vbase[(size_t)kp * D3_ + d]);
        }
        if (tid < 64) kseq[tid] = seq_id[b * L_ + kt * 64 + tid];
        __syncthreads();

        // S = Q K^T
        float S[8][4] = {};
#pragma unroll
        for (int ks = 0; ks < 8; ks++) {
            float4 a = *(const float4*)&Qp[(wid * 8 + ks) * 128 + lane * 4];
#pragma unroll
            for (int nt = 0; nt < 8; nt++) {
                float2 bv = *(const float2*)&Kp[(ks * 8 + nt) * 64 + lane * 2];
                mma8(S[nt], a, bv);
            }
        }
        // mask + scale + row max
        float mx0 = -1e30f, mx1 = -1e30f;
#pragma unroll
        for (int nt = 0; nt < 8; nt++) {
            int k0 = kseq[nt * 8 + c0], k1 = kseq[nt * 8 + c0 + 1];
            S[nt][0] = (qs0 == k0) ? S[nt][0] * 0.125f : -1e30f;
            S[nt][1] = (qs0 == k1) ? S[nt][1] * 0.125f : -1e30f;
            S[nt][2] = (qs1 == k0) ? S[nt][2] * 0.125f : -1e30f;
            S[nt][3] = (qs1 == k1) ? S[nt][3] * 0.125f : -1e30f;
            mx0 = fmaxf(mx0, fmaxf(S[nt][0], S[nt][1]));
            mx1 = fmaxf(mx1, fmaxf(S[nt][2], S[nt][3]));
        }
        mx0 = fmaxf(mx0, __shfl_xor_sync(0xffffffffu, mx0, 1));
        mx0 = fmaxf(mx0, __shfl_xor_sync(0xffffffffu, mx0, 2));
        mx1 = fmaxf(mx1, __shfl_xor_sync(0xffffffffu, mx1, 1));
        mx1 = fmaxf(mx1, __shfl_xor_sync(0xffffffffu, mx1, 2));
        float mn0 = fmaxf(m0v, mx0), mn1 = fmaxf(m1v, mx1);
        float al0 = __expf(m0v - mn0), al1 = __expf(m1v - mn1);
        m0v = mn0; m1v = mn1;

        float rs0 = 0.f, rs1 = 0.f;
#pragma unroll
        for (int nt = 0; nt < 8; nt++) {
            float p00 = (S[nt][0] <= -9e29f) ? 0.f : __expf(S[nt][0] - mn0);
            float p01 = (S[nt][1] <= -9e29f) ? 0.f : __expf(S[nt][1] - mn0);
            float p10 = (S[nt][2] <= -9e29f) ? 0.f : __expf(S[nt][2] - mn1);
            float p11 = (S[nt][3] <= -9e29f) ? 0.f : __expf(S[nt][3] - mn1);
            rs0 += p00 + p01;
            rs1 += p10 + p11;
            float* pb = &Pp[(wid * 8 + nt) * 128];
            pb[lA * 4 + rA]     = to_tf32(p00);
            pb[lB * 4 + rB]     = to_tf32(p01);
            pb[lA * 4 + rA + 1] = to_tf32(p10);
            pb[lB * 4 + rB + 1] = to_tf32(p11);
        }
        rs0 += __shfl_xor_sync(0xffffffffu, rs0, 1);
        rs0 += __shfl_xor_sync(0xffffffffu, rs0, 2);
        rs1 += __shfl_xor_sync(0xffffffffu, rs1, 1);
        rs1 += __shfl_xor_sync(0xffffffffu, rs1, 2);
        l0 = l0 * al0 + rs0;
        l1 = l1 * al1 + rs1;
#pragma unroll
        for (int nt = 0; nt < 8; nt++) {
            O[nt][0] *= al0; O[nt][1] *= al0;
            O[nt][2] *= al1; O[nt][3] *= al1;
        }
        __syncwarp();
        // O += P V
#pragma unroll
        for (int ks = 0; ks < 8; ks++) {
            float4 a = *(const float4*)&Pp[(wid * 8 + ks) * 128 + lane * 4];
#pragma unroll
            for (int nt = 0; nt < 8; nt++) {
                float2 bv = *(const float2*)&Vp[(ks * 8 + nt) * 64 + lane * 2];
                mma8(O[nt], a, bv);
            }
        }
    }
    // epilogue
    float inv0 = 1.0f / l0, inv1 = 1.0f / l1;
    int r0 = q0 + wid * 16 + (lane >> 2);
    float* obase = g_ctx + (rowOff + r0) * D_ + h * DH_ + (lane & 3) * 2;
#pragma unroll
    for (int nt = 0; nt < 8; nt++) {
        *(float2*)(obase + nt * 8) =
            make_float2(O[nt][0] * inv0, O[nt][1] * inv0);
        *(float2*)(obase + (size_t)8 * D_ + nt * 8) =
            make_float2(O[nt][2] * inv1, O[nt][3] * inv1);
    }
}

// ---------------- launch ----------------------------------------------------
extern "C" void kernel_launch(void* const* d_in, const int* in_sizes, int n_in,
                              void* d_out, int out_size) {
    const float* x    = (const float*)d_in[0];
    const int*   seq  = (const int*)d_in[1];
    const float* ln1w = (const float*)d_in[2];
    const float* ln1b = (const float*)d_in[3];
    const float* wqkv = (const float*)d_in[4];
    const float* qlnw = (const float*)d_in[5];
    const float* klnw = (const float*)d_in[6];
    const float* wout = (const float*)d_in[7];
    float* out = (float*)d_out;

    const int attn_smem = 16384 * 4 + 64 * 4;   // 65792 B
    cudaFuncSetAttribute(attn_tc_kernel,
                         cudaFuncAttributeMaxDynamicSharedMemorySize, attn_smem);

    rope_tab_kernel<<<L_, 32>>>();
    ln1_kernel<<<R_, 256>>>(x, ln1w, ln1b);
    gemm_qkv_kernel<<<dim3(D3_ / 128, R_ / 128), 256>>>(wqkv);
    qkln_rope_kernel<<<dim3(R_, 2), 256>>>(qlnw, klnw);
    attn_tc_kernel<<<dim3(L_ / 64, H_, B_), 128, attn_smem>>>(seq);
    gemm_out_kernel<<<dim3(D_ / 128, R_ / 128), 256>>>(wout, out);
}